// round 6
// baseline (speedup 1.0000x reference)
#include <cuda_runtime.h>
#include <stdint.h>
#include <math.h>

#define B_DIM 2
#define S_DIM 2048
#define M_DIM 1024
#define NHEAD 16
#define HDIM 64
#define FFN_H 2048
#define TOK (B_DIM * S_DIM)          // 4096
#define QKV_N (3 * M_DIM)            // 3072
#define NEGV -1e9f

// ------------------------- scratch (static device) -------------------------
__device__ float g_bqkv[QKV_N];
__device__ float g_qkv[TOK * QKV_N];
__device__ float g_ctx[TOK * M_DIM];
__device__ float g_attnproj[TOK * M_DIM];
__device__ float g_y[TOK * M_DIM];
__device__ float g_ffh[TOK * FFN_H];
__device__ float g_ffo[TOK * M_DIM];

// ------------------------- helpers -----------------------------------------
__device__ __forceinline__ void mma8(float* c, const unsigned* a, const unsigned* b) {
    asm volatile(
        "mma.sync.aligned.m16n8k8.row.col.f32.tf32.tf32.f32 "
        "{%0,%1,%2,%3},{%4,%5,%6,%7},{%8,%9},{%0,%1,%2,%3};"
        : "+f"(c[0]), "+f"(c[1]), "+f"(c[2]), "+f"(c[3])
        : "r"(a[0]), "r"(a[1]), "r"(a[2]), "r"(a[3]), "r"(b[0]), "r"(b[1]));
}
__device__ __forceinline__ void cp16(uint32_t dst, const void* src) {
    asm volatile("cp.async.cg.shared.global [%0], [%1], 16;\n" :: "r"(dst), "l"(src));
}
#define CP_COMMIT() asm volatile("cp.async.commit_group;\n" ::: "memory")
#define CP_WAIT(n)  asm volatile("cp.async.wait_group %0;\n" :: "n"(n) : "memory")

// pack QKV biases into [3072]
__global__ void pack_bias(const float* __restrict__ bq, const float* __restrict__ bk,
                          const float* __restrict__ bv) {
    int idx = blockIdx.x * blockDim.x + threadIdx.x;
    if (idx < QKV_N) {
        int which = idx / M_DIM, hd = idx % M_DIM;
        const float* bb = (which == 0) ? bq : (which == 1) ? bk : bv;
        g_bqkv[idx] = bb[hd];
    }
}

// ------------------------- tf32 tensor-core GEMM (cp.async, 3-stage) -------
// C[M,N] = A[M,K]@B + bias (optional ReLU).
// QKV=true: B is the per-head [H,M,D] triple (Wq,Wk,Wv), col n -> W[h,k,d].
// Tile 128x128, kstep 16, 256 thr (8 warps, 2x4), warp tile 64x32.
// smem/stage: A 128x20, B 16x136. 3 stages = 56832 B dynamic.
template <bool RELU, bool QKV>
__global__ __launch_bounds__(256, 2)
void gemm_tc(const float* __restrict__ A, const float* __restrict__ B0,
             const float* __restrict__ B1, const float* __restrict__ B2,
             const float* __restrict__ bias, float* __restrict__ C,
             int M, int N, int K) {
    extern __shared__ float sm[];
    float* Asm = sm;              // 3 * 2560
    float* Bsm = sm + 3 * 2560;   // 3 * 2176

    const int tid = threadIdx.x, lane = tid & 31, w = tid >> 5;
    const int wm = w >> 2, wn = w & 3;
    const int g = lane >> 2, tg = lane & 3;
    const int row0 = blockIdx.y * 128, col0 = blockIdx.x * 128;

    const int ar = tid >> 2, ac = (tid & 3) * 4;     // A rows ar, ar+64
    const int br = tid >> 5, bc = (tid & 31) * 4;    // B rows br, br+8

    // per-thread gmem bases
    const float* Ap0 = A + (size_t)(row0 + ar) * K + ac;
    const float* Ap1 = Ap0 + (size_t)64 * K;
    const float* Bb;
    size_t bstride;
    if (QKV) {
        int n = col0 + bc;
        const float* W = (n < M_DIM) ? B0 : (n < 2 * M_DIM) ? B1 : B2;
        int hd = n & (M_DIM - 1);
        Bb = W + ((size_t)(hd >> 6) * M_DIM) * HDIM + (hd & 63);
        bstride = HDIM;
    } else {
        Bb = B0 + col0 + bc;
        bstride = N;
    }

    // smem (shared-space) addresses
    uint32_t smA = (uint32_t)__cvta_generic_to_shared(Asm);
    uint32_t smB = (uint32_t)__cvta_generic_to_shared(Bsm);
    const uint32_t dA0 = smA + (ar * 20 + ac) * 4;
    const uint32_t dA1 = dA0 + 64 * 20 * 4;
    const uint32_t dB0 = smB + (br * 136 + bc) * 4;
    const uint32_t dB1 = dB0 + 8 * 136 * 4;

    float acc[4][4][4];
#pragma unroll
    for (int i = 0; i < 4; i++)
#pragma unroll
        for (int j = 0; j < 4; j++)
#pragma unroll
            for (int q = 0; q < 4; q++) acc[i][j][q] = 0.f;

    const int T = K >> 4;

    auto issue = [&](int s, int k0) {
        const uint32_t oa = s * 2560 * 4, ob = s * 2176 * 4;
        cp16(dA0 + oa, Ap0 + k0);
        cp16(dA1 + oa, Ap1 + k0);
        cp16(dB0 + ob, Bb + (size_t)(k0 + br) * bstride);
        cp16(dB1 + ob, Bb + (size_t)(k0 + br + 8) * bstride);
        CP_COMMIT();
    };

    issue(0, 0);
    issue(1, 16);

    for (int t = 0; t < T; t++) {
        if (t + 1 < T) { CP_WAIT(1); } else { CP_WAIT(0); }
        __syncthreads();

        const int cur = t % 3;
        const float* as = Asm + cur * 2560;
        const float* bs = Bsm + cur * 2176;

#pragma unroll
        for (int fk = 0; fk < 2; fk++) {
            unsigned af[4][4];
#pragma unroll
            for (int mi = 0; mi < 4; mi++) {
                const float* ap = as + (wm * 64 + mi * 16) * 20 + fk * 8;
                af[mi][0] = __float_as_uint(ap[g * 20 + tg]);
                af[mi][1] = __float_as_uint(ap[(g + 8) * 20 + tg]);
                af[mi][2] = __float_as_uint(ap[g * 20 + tg + 4]);
                af[mi][3] = __float_as_uint(ap[(g + 8) * 20 + tg + 4]);
            }
#pragma unroll
            for (int ni = 0; ni < 4; ni++) {
                unsigned bf[2];
                const int ncol = wn * 32 + ni * 8 + g;
                bf[0] = __float_as_uint(bs[(fk * 8 + tg) * 136 + ncol]);
                bf[1] = __float_as_uint(bs[(fk * 8 + tg + 4) * 136 + ncol]);
#pragma unroll
                for (int mi = 0; mi < 4; mi++) mma8(acc[mi][ni], af[mi], bf);
            }
        }
        __syncthreads();
        if (t + 2 < T) issue((t + 2) % 3, (t + 2) * 16);
    }

    // epilogue
#pragma unroll
    for (int mi = 0; mi < 4; mi++) {
        const int r = row0 + wm * 64 + mi * 16 + g;
#pragma unroll
        for (int ni = 0; ni < 4; ni++) {
            const int c = col0 + wn * 32 + ni * 8 + 2 * tg;
            const float b0 = bias[c], b1 = bias[c + 1];
            float v0 = acc[mi][ni][0] + b0, v1 = acc[mi][ni][1] + b1;
            float v2 = acc[mi][ni][2] + b0, v3 = acc[mi][ni][3] + b1;
            if (RELU) {
                v0 = fmaxf(v0, 0.f); v1 = fmaxf(v1, 0.f);
                v2 = fmaxf(v2, 0.f); v3 = fmaxf(v3, 0.f);
            }
            *(float2*)&C[(size_t)r * N + c] = make_float2(v0, v1);
            *(float2*)&C[(size_t)(r + 8) * N + c] = make_float2(v2, v3);
        }
    }
}

// ------------------------- tf32 flash attention (cp.async, 2-stage) --------
// grid (S/128, B*H), 256 thr = 8 warps; warp = 16 queries; key tile 64.
__global__ __launch_bounds__(256)
void attn_tc(const float* __restrict__ qkv, const int* __restrict__ mask,
             float* __restrict__ ctx) {
    extern __shared__ float sm[];
    // Ks[2][64*68] | Vs[2][64*68] | Pw0[8*16*68] | Ms[2][64]
    float* KsB = sm;
    float* VsB = sm + 2 * 4352;
    float* Pw0 = sm + 4 * 4352;
    float* MsB = Pw0 + 8704;

    const int tid = threadIdx.x, lane = tid & 31, w = tid >> 5;
    const int g = lane >> 2, tg = lane & 3;
    const int bh = blockIdx.y, b = bh >> 4, h = bh & 15;
    const int qw = blockIdx.x * 128 + w * 16;
    float* Pw = Pw0 + w * 16 * 68;

    const int kr = tid >> 4, kc = (tid & 15) * 4;
    uint32_t smbase = (uint32_t)__cvta_generic_to_shared(sm);
    const uint32_t dK = smbase + ((kr * 68 + kc)) * 4;
    const uint32_t dV = dK + 2 * 4352 * 4;

    auto issue = [&](int s, int kt) {
        const uint32_t off = s * 4352 * 4;
        const float* kb = qkv + (size_t)(b * S_DIM + kt + kr) * QKV_N + M_DIM + h * HDIM + kc;
#pragma unroll
        for (int i = 0; i < 4; i++) {
            const float* p = kb + (size_t)(i * 16) * QKV_N;
            cp16(dK + off + i * 16 * 68 * 4, p);
            cp16(dV + off + i * 16 * 68 * 4, p + M_DIM);
        }
        CP_COMMIT();
        if (tid < 64) MsB[s * 64 + tid] = mask[b * S_DIM + kt + tid] ? 0.f : NEGV;
    };

    // Q fragments (registers), pre-scaled by 1/sqrt(64)
    unsigned qf[8][4];
    {
        const float* qb = qkv + (size_t)(b * S_DIM + qw) * QKV_N + h * HDIM;
#pragma unroll
        for (int fk = 0; fk < 8; fk++) {
            qf[fk][0] = __float_as_uint(qb[(size_t)g * QKV_N + fk * 8 + tg] * 0.125f);
            qf[fk][1] = __float_as_uint(qb[(size_t)(g + 8) * QKV_N + fk * 8 + tg] * 0.125f);
            qf[fk][2] = __float_as_uint(qb[(size_t)g * QKV_N + fk * 8 + tg + 4] * 0.125f);
            qf[fk][3] = __float_as_uint(qb[(size_t)(g + 8) * QKV_N + fk * 8 + tg + 4] * 0.125f);
        }
    }

    float of[8][4];
#pragma unroll
    for (int i = 0; i < 8; i++) { of[i][0] = of[i][1] = of[i][2] = of[i][3] = 0.f; }
    float m0 = -INFINITY, m1 = -INFINITY, l0 = 0.f, l1 = 0.f;

    const int T = S_DIM / 64;
    issue(0, 0);

    for (int t = 0; t < T; t++) {
        if (t + 1 < T) { issue((t + 1) & 1, (t + 1) * 64); CP_WAIT(1); }
        else           { CP_WAIT(0); }
        __syncthreads();

        const int cur = t & 1;
        const float* Ks = KsB + cur * 4352;
        const float* Vs = VsB + cur * 4352;
        const float* Ms = MsB + cur * 64;

        // S = Q * K^T  (16 x 64 per warp)
        float s[8][4];
#pragma unroll
        for (int fn = 0; fn < 8; fn++) { s[fn][0] = s[fn][1] = s[fn][2] = s[fn][3] = 0.f; }
#pragma unroll
        for (int fk = 0; fk < 8; fk++) {
#pragma unroll
            for (int fn = 0; fn < 8; fn++) {
                unsigned bf[2];
                bf[0] = __float_as_uint(Ks[(fn * 8 + g) * 68 + fk * 8 + tg]);
                bf[1] = __float_as_uint(Ks[(fn * 8 + g) * 68 + fk * 8 + tg + 4]);
                mma8(s[fn], qf[fk], bf);
            }
        }

        // mask + online softmax (rows g and g+8)
        float mx0 = -INFINITY, mx1 = -INFINITY;
#pragma unroll
        for (int fn = 0; fn < 8; fn++) {
            const float mk0 = Ms[fn * 8 + 2 * tg], mk1 = Ms[fn * 8 + 2 * tg + 1];
            s[fn][0] += mk0; s[fn][1] += mk1;
            s[fn][2] += mk0; s[fn][3] += mk1;
            mx0 = fmaxf(mx0, fmaxf(s[fn][0], s[fn][1]));
            mx1 = fmaxf(mx1, fmaxf(s[fn][2], s[fn][3]));
        }
        mx0 = fmaxf(mx0, __shfl_xor_sync(0xffffffffu, mx0, 1));
        mx0 = fmaxf(mx0, __shfl_xor_sync(0xffffffffu, mx0, 2));
        mx1 = fmaxf(mx1, __shfl_xor_sync(0xffffffffu, mx1, 1));
        mx1 = fmaxf(mx1, __shfl_xor_sync(0xffffffffu, mx1, 2));
        const float nm0 = fmaxf(m0, mx0), nm1 = fmaxf(m1, mx1);
        const float a0 = __expf(m0 - nm0), a1 = __expf(m1 - nm1);
        m0 = nm0; m1 = nm1;
        l0 *= a0; l1 *= a1;
#pragma unroll
        for (int fn = 0; fn < 8; fn++) {
            of[fn][0] *= a0; of[fn][1] *= a0;
            of[fn][2] *= a1; of[fn][3] *= a1;
            float p0 = __expf(s[fn][0] - m0);
            float p1 = __expf(s[fn][1] - m0);
            float p2 = __expf(s[fn][2] - m1);
            float p3 = __expf(s[fn][3] - m1);
            l0 += p0 + p1; l1 += p2 + p3;
            *(float2*)&Pw[g * 68 + fn * 8 + 2 * tg] = make_float2(p0, p1);
            *(float2*)&Pw[(g + 8) * 68 + fn * 8 + 2 * tg] = make_float2(p2, p3);
        }
        __syncwarp();

        // O += P * V
#pragma unroll
        for (int fk = 0; fk < 8; fk++) {
            unsigned af[4];
            af[0] = __float_as_uint(Pw[g * 68 + fk * 8 + tg]);
            af[1] = __float_as_uint(Pw[(g + 8) * 68 + fk * 8 + tg]);
            af[2] = __float_as_uint(Pw[g * 68 + fk * 8 + tg + 4]);
            af[3] = __float_as_uint(Pw[(g + 8) * 68 + fk * 8 + tg + 4]);
#pragma unroll
            for (int fn = 0; fn < 8; fn++) {
                unsigned bf[2];
                bf[0] = __float_as_uint(Vs[(fk * 8 + tg) * 68 + fn * 8 + g]);
                bf[1] = __float_as_uint(Vs[(fk * 8 + tg + 4) * 68 + fn * 8 + g]);
                mma8(of[fn], af, bf);
            }
        }
        __syncthreads();   // all warps done reading stage before overwrite
    }

    // cross-lane reduce of row sums (quad covers 64 cols in 4 lanes)
    l0 += __shfl_xor_sync(0xffffffffu, l0, 1);
    l0 += __shfl_xor_sync(0xffffffffu, l0, 2);
    l1 += __shfl_xor_sync(0xffffffffu, l1, 1);
    l1 += __shfl_xor_sync(0xffffffffu, l1, 2);

    const float i0 = 1.f / fmaxf(l0, 1e-30f), i1 = 1.f / fmaxf(l1, 1e-30f);
    float* cb = ctx + (size_t)(b * S_DIM + qw) * M_DIM + h * HDIM;
#pragma unroll
    for (int fn = 0; fn < 8; fn++) {
        *(float2*)&cb[(size_t)g * M_DIM + fn * 8 + 2 * tg] =
            make_float2(of[fn][0] * i0, of[fn][1] * i0);
        *(float2*)&cb[(size_t)(g + 8) * M_DIM + fn * 8 + 2 * tg] =
            make_float2(of[fn][2] * i1, of[fn][3] * i1);
    }
}

// ------------------------- residual + layernorm ----------------------------
__global__ __launch_bounds__(256)
void ln_kernel(const float* __restrict__ A, const float* __restrict__ R,
               const float* __restrict__ g, const float* __restrict__ be,
               float* __restrict__ out) {
    __shared__ float red[8];
    __shared__ float bcast;
    const int row = blockIdx.x;
    const int tid = threadIdx.x;

    float4 a = ((const float4*)(A + (size_t)row * M_DIM))[tid];
    float4 r = ((const float4*)(R + (size_t)row * M_DIM))[tid];
    float v0 = a.x + r.x, v1 = a.y + r.y, v2 = a.z + r.z, v3 = a.w + r.w;

    float s = v0 + v1 + v2 + v3;
#pragma unroll
    for (int off = 16; off; off >>= 1) s += __shfl_xor_sync(0xffffffffu, s, off);
    if ((tid & 31) == 0) red[tid >> 5] = s;
    __syncthreads();
    if (tid == 0) {
        float t = 0.f;
#pragma unroll
        for (int i = 0; i < 8; i++) t += red[i];
        bcast = t * (1.f / M_DIM);
    }
    __syncthreads();
    const float mu = bcast;

    float d0 = v0 - mu, d1 = v1 - mu, d2 = v2 - mu, d3 = v3 - mu;
    float s2 = d0 * d0 + d1 * d1 + d2 * d2 + d3 * d3;
#pragma unroll
    for (int off = 16; off; off >>= 1) s2 += __shfl_xor_sync(0xffffffffu, s2, off);
    __syncthreads();
    if ((tid & 31) == 0) red[tid >> 5] = s2;
    __syncthreads();
    if (tid == 0) {
        float t = 0.f;
#pragma unroll
        for (int i = 0; i < 8; i++) t += red[i];
        bcast = rsqrtf(t * (1.f / M_DIM) + 1e-5f);
    }
    __syncthreads();
    const float rstd = bcast;

    float4 gg = ((const float4*)g)[tid];
    float4 bb = ((const float4*)be)[tid];
    float4 o;
    o.x = d0 * rstd * gg.x + bb.x;
    o.y = d1 * rstd * gg.y + bb.y;
    o.z = d2 * rstd * gg.z + bb.z;
    o.w = d3 * rstd * gg.w + bb.w;
    ((float4*)(out + (size_t)row * M_DIM))[tid] = o;
}

// ---------------------------------------------------------------------------
extern "C" void kernel_launch(void* const* d_in, const int* in_sizes, int n_in,
                              void* d_out, int out_size) {
    const float* x     = (const float*)d_in[0];
    const int*   amask = (const int*)  d_in[1];
    const float* Wq    = (const float*)d_in[2];
    const float* bq    = (const float*)d_in[3];
    const float* Wk    = (const float*)d_in[4];
    const float* bk    = (const float*)d_in[5];
    const float* Wv    = (const float*)d_in[6];
    const float* bv    = (const float*)d_in[7];
    const float* Wo    = (const float*)d_in[8];
    const float* bo    = (const float*)d_in[9];
    const float* g1    = (const float*)d_in[10];
    const float* b1    = (const float*)d_in[11];
    const float* W1    = (const float*)d_in[12];
    const float* bias1 = (const float*)d_in[13];
    const float* W2    = (const float*)d_in[14];
    const float* bias2 = (const float*)d_in[15];
    const float* g2    = (const float*)d_in[16];
    const float* b2    = (const float*)d_in[17];
    float* out = (float*)d_out;

    float *bqkv, *qkv, *ctx, *attnproj, *y, *ffh, *ffo;
    cudaGetSymbolAddress((void**)&bqkv,     g_bqkv);
    cudaGetSymbolAddress((void**)&qkv,      g_qkv);
    cudaGetSymbolAddress((void**)&ctx,      g_ctx);
    cudaGetSymbolAddress((void**)&attnproj, g_attnproj);
    cudaGetSymbolAddress((void**)&y,        g_y);
    cudaGetSymbolAddress((void**)&ffh,      g_ffh);
    cudaGetSymbolAddress((void**)&ffo,      g_ffo);

    const int gemm_smem = 3 * (2560 + 2176) * sizeof(float);      // 56832
    const int attn_smem = (4 * 4352 + 8704 + 128) * sizeof(float); // 104960
    cudaFuncSetAttribute(gemm_tc<false, true>,  cudaFuncAttributeMaxDynamicSharedMemorySize, gemm_smem);
    cudaFuncSetAttribute(gemm_tc<false, false>, cudaFuncAttributeMaxDynamicSharedMemorySize, gemm_smem);
    cudaFuncSetAttribute(gemm_tc<true, false>,  cudaFuncAttributeMaxDynamicSharedMemorySize, gemm_smem);
    cudaFuncSetAttribute(attn_tc, cudaFuncAttributeMaxDynamicSharedMemorySize, attn_smem);

    // 1) bias pack (tiny)
    pack_bias<<<(QKV_N + 255) / 256, 256>>>(bq, bk, bv);

    // 2) fused QKV projection (reads Wq/Wk/Wv in-place)
    {
        dim3 grid(QKV_N / 128, TOK / 128);
        gemm_tc<false, true><<<grid, 256, gemm_smem>>>(x, Wq, Wk, Wv, bqkv, qkv,
                                                       TOK, QKV_N, M_DIM);
    }

    // 3) attention
    {
        dim3 grid(S_DIM / 128, B_DIM * NHEAD);
        attn_tc<<<grid, 256, attn_smem>>>(qkv, amask, ctx);
    }

    // 4) output projection
    {
        dim3 grid(M_DIM / 128, TOK / 128);
        gemm_tc<false, false><<<grid, 256, gemm_smem>>>(ctx, Wo, nullptr, nullptr,
                                                        bo, attnproj, TOK, M_DIM, M_DIM);
    }

    // 5) y = LN(attnproj + x)
    ln_kernel<<<TOK, 256>>>(attnproj, x, g1, b1, y);

    // 6) ffh = relu(y @ W1 + bias1)
    {
        dim3 grid(FFN_H / 128, TOK / 128);
        gemm_tc<true, false><<<grid, 256, gemm_smem>>>(y, W1, nullptr, nullptr,
                                                       bias1, ffh, TOK, FFN_H, M_DIM);
    }

    // 7) ffo = ffh @ W2 + bias2
    {
        dim3 grid(M_DIM / 128, TOK / 128);
        gemm_tc<false, false><<<grid, 256, gemm_smem>>>(ffh, W2, nullptr, nullptr,
                                                        bias2, ffo, TOK, M_DIM, FFN_H);
    }

    // 8) out = LN(y + ffo)
    ln_kernel<<<TOK, 256>>>(ffo, y, g2, b2, out);
}

// round 8
// speedup vs baseline: 1.4467x; 1.4467x over previous
#include <cuda_runtime.h>
#include <stdint.h>
#include <math.h>

#define B_DIM 2
#define S_DIM 2048
#define M_DIM 1024
#define NHEAD 16
#define HDIM 64
#define FFN_H 2048
#define TOK (B_DIM * S_DIM)          // 4096
#define QKV_N (3 * M_DIM)            // 3072
#define NEGV -1e9f

// ------------------------- scratch (static device) -------------------------
__device__ float g_Wqkv[M_DIM * QKV_N];        // packed [K=1024, N=3072]
__device__ float g_bqkv[QKV_N];
__device__ float g_qkv[TOK * QKV_N];
__device__ float g_ctx[TOK * M_DIM];
__device__ float g_attnproj[TOK * M_DIM];
__device__ float g_y[TOK * M_DIM];
__device__ float g_ffh[TOK * FFN_H];
__device__ float g_ffo[TOK * M_DIM];

// ------------------------- tf32 helpers ------------------------------------
__device__ __forceinline__ float tf32r(float x) {
    unsigned r; asm("cvt.rna.tf32.f32 %0, %1;" : "=r"(r) : "f"(x));
    return __uint_as_float(r);
}
__device__ __forceinline__ void mma8(float* c, const unsigned* a, const unsigned* b) {
    asm volatile(
        "mma.sync.aligned.m16n8k8.row.col.f32.tf32.tf32.f32 "
        "{%0,%1,%2,%3},{%4,%5,%6,%7},{%8,%9},{%0,%1,%2,%3};"
        : "+f"(c[0]), "+f"(c[1]), "+f"(c[2]), "+f"(c[3])
        : "r"(a[0]), "r"(a[1]), "r"(a[2]), "r"(a[3]), "r"(b[0]), "r"(b[1]));
}

// ------------------------- weight repack -----------------------------------
__global__ void pack_qkv_kernel(const float* __restrict__ Wq,
                                const float* __restrict__ Wk,
                                const float* __restrict__ Wv,
                                const float* __restrict__ bq,
                                const float* __restrict__ bk,
                                const float* __restrict__ bv) {
    int idx = blockIdx.x * blockDim.x + threadIdx.x;
    if (idx < M_DIM * QKV_N) {
        int n = idx % QKV_N;
        int k = idx / QKV_N;
        int which = n / M_DIM;
        int hd = n % M_DIM;
        int h = hd / HDIM, d = hd % HDIM;
        const float* W = (which == 0) ? Wq : (which == 1) ? Wk : Wv;
        g_Wqkv[idx] = W[((size_t)h * M_DIM + k) * HDIM + d];
    }
    if (idx < QKV_N) {
        int which = idx / M_DIM;
        int hd = idx % M_DIM;
        const float* bb = (which == 0) ? bq : (which == 1) ? bk : bv;
        g_bqkv[idx] = bb[hd];
    }
}

// ------------------------- tf32 tensor-core GEMM ---------------------------
// Round-4 structure (register-staged double buffer), dynamic smem, 2 CTA/SM.
// C[M,N] = A[M,K]@B[K,N] + bias, optional ReLU. Tile 128x128, K-step 16,
// 256 thr = 8 warps (2x4), warp tile 64x32.
template <bool RELU>
__global__ __launch_bounds__(256, 2)
void gemm_tc(const float* __restrict__ A, const float* __restrict__ Bm,
             const float* __restrict__ bias, float* __restrict__ C,
             int M, int N, int K) {
    extern __shared__ float smdyn[];
    // As[2][128][20] then Bs[2][16][136]
    float* As = smdyn;                 // 2 * 2560
    float* Bs = smdyn + 2 * 2560;      // 2 * 2176

    const int tid = threadIdx.x, lane = tid & 31, w = tid >> 5;
    const int wm = w >> 2, wn = w & 3;
    const int g = lane >> 2, tg = lane & 3;
    const int row0 = blockIdx.y * 128, col0 = blockIdx.x * 128;

    const int ar = tid >> 2, ac = (tid & 3) * 4;     // A rows ar, ar+64
    const int br = tid >> 5, bc = (tid & 31) * 4;    // B rows br, br+8

    float4 stA[2], stB[2];
    float acc[4][4][4];
#pragma unroll
    for (int i = 0; i < 4; i++)
#pragma unroll
        for (int j = 0; j < 4; j++)
#pragma unroll
            for (int q = 0; q < 4; q++) acc[i][j][q] = 0.f;

    const int nk = K >> 4;

    // prologue: load + store stage 0
    {
        const float* Ap = A + (size_t)(row0 + ar) * K + ac;
        stA[0] = *(const float4*)Ap;
        stA[1] = *(const float4*)(Ap + (size_t)64 * K);
        const float* Bp = Bm + (size_t)br * N + col0 + bc;
        stB[0] = *(const float4*)Bp;
        stB[1] = *(const float4*)(Bp + (size_t)8 * N);
#pragma unroll
        for (int i = 0; i < 2; i++) {
            float4 v = stA[i];
            float* ad = &As[0 * 2560 + (ar + i * 64) * 20 + ac];
            ad[0] = tf32r(v.x); ad[1] = tf32r(v.y); ad[2] = tf32r(v.z); ad[3] = tf32r(v.w);
            v = stB[i];
            float* bd = &Bs[0 * 2176 + (br + i * 8) * 136 + bc];
            bd[0] = tf32r(v.x); bd[1] = tf32r(v.y); bd[2] = tf32r(v.z); bd[3] = tf32r(v.w);
        }
    }
    __syncthreads();

    for (int kt = 0; kt < nk; kt++) {
        const int cur = kt & 1;
        if (kt + 1 < nk) {
            const int k0 = (kt + 1) << 4;
            const float* Ap = A + (size_t)(row0 + ar) * K + k0 + ac;
            stA[0] = *(const float4*)Ap;
            stA[1] = *(const float4*)(Ap + (size_t)64 * K);
            const float* Bp = Bm + (size_t)(k0 + br) * N + col0 + bc;
            stB[0] = *(const float4*)Bp;
            stB[1] = *(const float4*)(Bp + (size_t)8 * N);
        }

        const float* as = As + cur * 2560;
        const float* bs = Bs + cur * 2176;
#pragma unroll
        for (int fk = 0; fk < 2; fk++) {
            unsigned af[4][4];
#pragma unroll
            for (int mi = 0; mi < 4; mi++) {
                const float* ap = as + (wm * 64 + mi * 16) * 20 + fk * 8;
                af[mi][0] = __float_as_uint(ap[g * 20 + tg]);
                af[mi][1] = __float_as_uint(ap[(g + 8) * 20 + tg]);
                af[mi][2] = __float_as_uint(ap[g * 20 + tg + 4]);
                af[mi][3] = __float_as_uint(ap[(g + 8) * 20 + tg + 4]);
            }
#pragma unroll
            for (int ni = 0; ni < 4; ni++) {
                unsigned bf[2];
                const int ncol = wn * 32 + ni * 8 + g;
                bf[0] = __float_as_uint(bs[(fk * 8 + tg) * 136 + ncol]);
                bf[1] = __float_as_uint(bs[(fk * 8 + tg + 4) * 136 + ncol]);
#pragma unroll
                for (int mi = 0; mi < 4; mi++) mma8(acc[mi][ni], af[mi], bf);
            }
        }

        if (kt + 1 < nk) {
            const int nxt = (kt + 1) & 1;
#pragma unroll
            for (int i = 0; i < 2; i++) {
                float4 v = stA[i];
                float* ad = &As[nxt * 2560 + (ar + i * 64) * 20 + ac];
                ad[0] = tf32r(v.x); ad[1] = tf32r(v.y); ad[2] = tf32r(v.z); ad[3] = tf32r(v.w);
                v = stB[i];
                float* bd = &Bs[nxt * 2176 + (br + i * 8) * 136 + bc];
                bd[0] = tf32r(v.x); bd[1] = tf32r(v.y); bd[2] = tf32r(v.z); bd[3] = tf32r(v.w);
            }
        }
        __syncthreads();
    }

    // epilogue
#pragma unroll
    for (int mi = 0; mi < 4; mi++) {
        const int r = row0 + wm * 64 + mi * 16 + g;
#pragma unroll
        for (int ni = 0; ni < 4; ni++) {
            const int c = col0 + wn * 32 + ni * 8 + 2 * tg;
            const float b0 = bias[c], b1 = bias[c + 1];
            float v0 = acc[mi][ni][0] + b0, v1 = acc[mi][ni][1] + b1;
            float v2 = acc[mi][ni][2] + b0, v3 = acc[mi][ni][3] + b1;
            if (RELU) {
                v0 = fmaxf(v0, 0.f); v1 = fmaxf(v1, 0.f);
                v2 = fmaxf(v2, 0.f); v3 = fmaxf(v3, 0.f);
            }
            *(float2*)&C[(size_t)r * N + c] = make_float2(v0, v1);
            *(float2*)&C[(size_t)(r + 8) * N + c] = make_float2(v2, v3);
        }
    }
}

// ------------------------- tf32 flash attention ----------------------------
// grid (S/128, B*H), 256 thr = 8 warps; warp = 16 queries; key tile 64.
__global__ __launch_bounds__(256, 2)
void attn_tc(const float* __restrict__ qkv, const int* __restrict__ mask,
             float* __restrict__ ctx) {
    extern __shared__ float sm[];
    float* Ks  = sm;                       // [64][68]
    float* Vs  = sm + 64 * 68;             // [64][68]
    float* Pw0 = sm + 2 * 64 * 68;         // [8][16][68]
    float* Ms  = Pw0 + 8 * 16 * 68;        // [64]

    const int tid = threadIdx.x, lane = tid & 31, w = tid >> 5;
    const int g = lane >> 2, tg = lane & 3;
    const int bh = blockIdx.y, b = bh >> 4, h = bh & 15;
    const int qw = blockIdx.x * 128 + w * 16;
    float* Pw = Pw0 + w * 16 * 68;

    unsigned qf[8][4];
    {
        const float* qb = qkv + (size_t)(b * S_DIM + qw) * QKV_N + h * HDIM;
#pragma unroll
        for (int fk = 0; fk < 8; fk++) {
            qf[fk][0] = __float_as_uint(tf32r(qb[(size_t)g * QKV_N + fk * 8 + tg] * 0.125f));
            qf[fk][1] = __float_as_uint(tf32r(qb[(size_t)(g + 8) * QKV_N + fk * 8 + tg] * 0.125f));
            qf[fk][2] = __float_as_uint(tf32r(qb[(size_t)g * QKV_N + fk * 8 + tg + 4] * 0.125f));
            qf[fk][3] = __float_as_uint(tf32r(qb[(size_t)(g + 8) * QKV_N + fk * 8 + tg + 4] * 0.125f));
        }
    }

    float of[8][4];
#pragma unroll
    for (int i = 0; i < 8; i++) { of[i][0] = of[i][1] = of[i][2] = of[i][3] = 0.f; }
    float m0 = -INFINITY, m1 = -INFINITY, l0 = 0.f, l1 = 0.f;

    const int kr = tid >> 4, kc = (tid & 15) * 4;

    for (int kt = 0; kt < S_DIM; kt += 64) {
        __syncthreads();
#pragma unroll
        for (int i = 0; i < 4; i++) {
            const int r = kr + i * 16;
            const float* kb = qkv + (size_t)(b * S_DIM + kt + r) * QKV_N + M_DIM + h * HDIM + kc;
            float4 kv = *(const float4*)kb;
            float4 vv = *(const float4*)(kb + M_DIM);
            float* kd = &Ks[r * 68 + kc];
            kd[0] = tf32r(kv.x); kd[1] = tf32r(kv.y);
            kd[2] = tf32r(kv.z); kd[3] = tf32r(kv.w);
            float* vd = &Vs[r * 68 + kc];
            vd[0] = tf32r(vv.x); vd[1] = tf32r(vv.y);
            vd[2] = tf32r(vv.z); vd[3] = tf32r(vv.w);
        }
        if (tid < 64) Ms[tid] = mask[b * S_DIM + kt + tid] ? 0.f : NEGV;
        __syncthreads();

        float s[8][4];
#pragma unroll
        for (int fn = 0; fn < 8; fn++) { s[fn][0] = s[fn][1] = s[fn][2] = s[fn][3] = 0.f; }
#pragma unroll
        for (int fk = 0; fk < 8; fk++) {
#pragma unroll
            for (int fn = 0; fn < 8; fn++) {
                unsigned bf[2];
                bf[0] = __float_as_uint(Ks[(fn * 8 + g) * 68 + fk * 8 + tg]);
                bf[1] = __float_as_uint(Ks[(fn * 8 + g) * 68 + fk * 8 + tg + 4]);
                mma8(s[fn], qf[fk], bf);
            }
        }

        float mx0 = -INFINITY, mx1 = -INFINITY;
#pragma unroll
        for (int fn = 0; fn < 8; fn++) {
            const float mk0 = Ms[fn * 8 + 2 * tg], mk1 = Ms[fn * 8 + 2 * tg + 1];
            s[fn][0] += mk0; s[fn][1] += mk1;
            s[fn][2] += mk0; s[fn][3] += mk1;
            mx0 = fmaxf(mx0, fmaxf(s[fn][0], s[fn][1]));
            mx1 = fmaxf(mx1, fmaxf(s[fn][2], s[fn][3]));
        }
        mx0 = fmaxf(mx0, __shfl_xor_sync(0xffffffffu, mx0, 1));
        mx0 = fmaxf(mx0, __shfl_xor_sync(0xffffffffu, mx0, 2));
        mx1 = fmaxf(mx1, __shfl_xor_sync(0xffffffffu, mx1, 1));
        mx1 = fmaxf(mx1, __shfl_xor_sync(0xffffffffu, mx1, 2));
        const float nm0 = fmaxf(m0, mx0), nm1 = fmaxf(m1, mx1);
        const float a0 = __expf(m0 - nm0), a1 = __expf(m1 - nm1);
        m0 = nm0; m1 = nm1;
        l0 *= a0; l1 *= a1;
#pragma unroll
        for (int fn = 0; fn < 8; fn++) {
            of[fn][0] *= a0; of[fn][1] *= a0;
            of[fn][2] *= a1; of[fn][3] *= a1;
            float p0 = tf32r(__expf(s[fn][0] - m0));
            float p1 = tf32r(__expf(s[fn][1] - m0));
            float p2 = tf32r(__expf(s[fn][2] - m1));
            float p3 = tf32r(__expf(s[fn][3] - m1));
            l0 += p0 + p1; l1 += p2 + p3;
            *(float2*)&Pw[g * 68 + fn * 8 + 2 * tg] = make_float2(p0, p1);
            *(float2*)&Pw[(g + 8) * 68 + fn * 8 + 2 * tg] = make_float2(p2, p3);
        }
        __syncwarp();

#pragma unroll
        for (int fk = 0; fk < 8; fk++) {
            unsigned af[4];
            af[0] = __float_as_uint(Pw[g * 68 + fk * 8 + tg]);
            af[1] = __float_as_uint(Pw[(g + 8) * 68 + fk * 8 + tg]);
            af[2] = __float_as_uint(Pw[g * 68 + fk * 8 + tg + 4]);
            af[3] = __float_as_uint(Pw[(g + 8) * 68 + fk * 8 + tg + 4]);
#pragma unroll
            for (int fn = 0; fn < 8; fn++) {
                unsigned bf[2];
                bf[0] = __float_as_uint(Vs[(fk * 8 + tg) * 68 + fn * 8 + g]);
                bf[1] = __float_as_uint(Vs[(fk * 8 + tg + 4) * 68 + fn * 8 + g]);
                mma8(of[fn], af, bf);
            }
        }
        __syncwarp();
    }

    l0 += __shfl_xor_sync(0xffffffffu, l0, 1);
    l0 += __shfl_xor_sync(0xffffffffu, l0, 2);
    l1 += __shfl_xor_sync(0xffffffffu, l1, 1);
    l1 += __shfl_xor_sync(0xffffffffu, l1, 2);

    const float i0 = 1.f / fmaxf(l0, 1e-30f), i1 = 1.f / fmaxf(l1, 1e-30f);
    float* cb = ctx + (size_t)(b * S_DIM + qw) * M_DIM + h * HDIM;
#pragma unroll
    for (int fn = 0; fn < 8; fn++) {
        *(float2*)&cb[(size_t)g * M_DIM + fn * 8 + 2 * tg] =
            make_float2(of[fn][0] * i0, of[fn][1] * i0);
        *(float2*)&cb[(size_t)(g + 8) * M_DIM + fn * 8 + 2 * tg] =
            make_float2(of[fn][2] * i1, of[fn][3] * i1);
    }
}

// ------------------------- residual + layernorm ----------------------------
__global__ __launch_bounds__(256)
void ln_kernel(const float* __restrict__ A, const float* __restrict__ R,
               const float* __restrict__ g, const float* __restrict__ be,
               float* __restrict__ out) {
    __shared__ float red[8];
    __shared__ float bcast;
    const int row = blockIdx.x;
    const int tid = threadIdx.x;

    float4 a = ((const float4*)(A + (size_t)row * M_DIM))[tid];
    float4 r = ((const float4*)(R + (size_t)row * M_DIM))[tid];
    float v0 = a.x + r.x, v1 = a.y + r.y, v2 = a.z + r.z, v3 = a.w + r.w;

    float s = v0 + v1 + v2 + v3;
#pragma unroll
    for (int off = 16; off; off >>= 1) s += __shfl_xor_sync(0xffffffffu, s, off);
    if ((tid & 31) == 0) red[tid >> 5] = s;
    __syncthreads();
    if (tid == 0) {
        float t = 0.f;
#pragma unroll
        for (int i = 0; i < 8; i++) t += red[i];
        bcast = t * (1.f / M_DIM);
    }
    __syncthreads();
    const float mu = bcast;

    float d0 = v0 - mu, d1 = v1 - mu, d2 = v2 - mu, d3 = v3 - mu;
    float s2 = d0 * d0 + d1 * d1 + d2 * d2 + d3 * d3;
#pragma unroll
    for (int off = 16; off; off >>= 1) s2 += __shfl_xor_sync(0xffffffffu, s2, off);
    __syncthreads();
    if ((tid & 31) == 0) red[tid >> 5] = s2;
    __syncthreads();
    if (tid == 0) {
        float t = 0.f;
#pragma unroll
        for (int i = 0; i < 8; i++) t += red[i];
        bcast = rsqrtf(t * (1.f / M_DIM) + 1e-5f);
    }
    __syncthreads();
    const float rstd = bcast;

    float4 gg = ((const float4*)g)[tid];
    float4 bb = ((const float4*)be)[tid];
    float4 o;
    o.x = d0 * rstd * gg.x + bb.x;
    o.y = d1 * rstd * gg.y + bb.y;
    o.z = d2 * rstd * gg.z + bb.z;
    o.w = d3 * rstd * gg.w + bb.w;
    ((float4*)(out + (size_t)row * M_DIM))[tid] = o;
}

// ---------------------------------------------------------------------------
extern "C" void kernel_launch(void* const* d_in, const int* in_sizes, int n_in,
                              void* d_out, int out_size) {
    const float* x     = (const float*)d_in[0];
    const int*   amask = (const int*)  d_in[1];
    const float* Wq    = (const float*)d_in[2];
    const float* bq    = (const float*)d_in[3];
    const float* Wk    = (const float*)d_in[4];
    const float* bk    = (const float*)d_in[5];
    const float* Wv    = (const float*)d_in[6];
    const float* bv    = (const float*)d_in[7];
    const float* Wo    = (const float*)d_in[8];
    const float* bo    = (const float*)d_in[9];
    const float* g1    = (const float*)d_in[10];
    const float* b1    = (const float*)d_in[11];
    const float* W1    = (const float*)d_in[12];
    const float* bias1 = (const float*)d_in[13];
    const float* W2    = (const float*)d_in[14];
    const float* bias2 = (const float*)d_in[15];
    const float* g2    = (const float*)d_in[16];
    const float* b2    = (const float*)d_in[17];
    float* out = (float*)d_out;

    float *Wqkv, *bqkv, *qkv, *ctx, *attnproj, *y, *ffh, *ffo;
    cudaGetSymbolAddress((void**)&Wqkv,     g_Wqkv);
    cudaGetSymbolAddress((void**)&bqkv,     g_bqkv);
    cudaGetSymbolAddress((void**)&qkv,      g_qkv);
    cudaGetSymbolAddress((void**)&ctx,      g_ctx);
    cudaGetSymbolAddress((void**)&attnproj, g_attnproj);
    cudaGetSymbolAddress((void**)&y,        g_y);
    cudaGetSymbolAddress((void**)&ffh,      g_ffh);
    cudaGetSymbolAddress((void**)&ffo,      g_ffo);

    const int gemm_smem = 2 * (2560 + 2176) * sizeof(float);       // 37888
    const int attn_smem = (2 * 64 * 68 + 8 * 16 * 68 + 64) * sizeof(float); // 69888
    cudaFuncSetAttribute(gemm_tc<false>, cudaFuncAttributeMaxDynamicSharedMemorySize, gemm_smem);
    cudaFuncSetAttribute(gemm_tc<true>,  cudaFuncAttributeMaxDynamicSharedMemorySize, gemm_smem);
    cudaFuncSetAttribute(attn_tc, cudaFuncAttributeMaxDynamicSharedMemorySize, attn_smem);

    // 1) pack per-head QKV weights
    pack_qkv_kernel<<<(M_DIM * QKV_N + 255) / 256, 256>>>(Wq, Wk, Wv, bq, bk, bv);

    // 2) fused QKV projection
    gemm_tc<false><<<dim3(QKV_N / 128, TOK / 128), 256, gemm_smem>>>(
        x, Wqkv, bqkv, qkv, TOK, QKV_N, M_DIM);

    // 3) attention
    attn_tc<<<dim3(S_DIM / 128, B_DIM * NHEAD), 256, attn_smem>>>(qkv, amask, ctx);

    // 4) output projection
    gemm_tc<false><<<dim3(M_DIM / 128, TOK / 128), 256, gemm_smem>>>(
        ctx, Wo, bo, attnproj, TOK, M_DIM, M_DIM);

    // 5) y = LN(attnproj + x)
    ln_kernel<<<TOK, 256>>>(attnproj, x, g1, b1, y);

    // 6) ffh = relu(y @ W1 + bias1)
    gemm_tc<true><<<dim3(FFN_H / 128, TOK / 128), 256, gemm_smem>>>(
        y, W1, bias1, ffh, TOK, FFN_H, M_DIM);

    // 7) ffo = ffh @ W2 + bias2
    gemm_tc<false><<<dim3(M_DIM / 128, TOK / 128), 256, gemm_smem>>>(
        ffh, W2, bias2, ffo, TOK, M_DIM, FFN_H);

    // 8) out = LN(y + ffo)
    ln_kernel<<<TOK, 256>>>(ffo, y, g2, b2, out);
}